// round 16
// baseline (speedup 1.0000x reference)
#include <cuda_runtime.h>
#include <cuda_bf16.h>
#include <cstdint>
#include <math.h>

#define T_DIM 8192
#define D_DIM 4096
#define E_DIM 64
#define SPLITK 4
#define KSPLIT (D_DIM / SPLITK)   // 1024
#define NKS (KSPLIT / 16)         // 64 k16-steps per split
#define GAP_TAU 4e-4f

// ---------------------------------------------------------------------------
// device globals (static allocations; no runtime mallocs)
// ---------------------------------------------------------------------------
// split-K partial sums: [split][row*64+col], fp32
__device__ __align__(16) float g_ws[SPLITK * T_DIM * E_DIM];          // 8 MB
// B in mma-fragment order: idx = ks*512 + t*256 + nb*32 + lane -> uint2{b0,b1}
__device__ __align__(16) uint2 g_Bfrag[(D_DIM / 16) * 2 * 8 * 32];    // 1 MB

// ---------------------------------------------------------------------------
// helpers
// ---------------------------------------------------------------------------
__device__ __forceinline__ void mma_bf16(float* c, const uint32_t* a,
                                         uint32_t b0, uint32_t b1) {
    asm volatile(
        "mma.sync.aligned.m16n8k16.row.col.f32.bf16.bf16.f32 "
        "{%0,%1,%2,%3}, {%4,%5,%6,%7}, {%8,%9}, {%0,%1,%2,%3};"
        : "+f"(c[0]), "+f"(c[1]), "+f"(c[2]), "+f"(c[3])
        : "r"(a[0]), "r"(a[1]), "r"(a[2]), "r"(a[3]), "r"(b0), "r"(b1));
}
// packed rn conversion: result.lo = bf16(x), result.hi = bf16(y)
__device__ __forceinline__ uint32_t cvt_bf16x2_rn(float x, float y) {
    uint32_t r;
    asm("cvt.rn.bf16x2.f32 %0, %1, %2;" : "=r"(r) : "f"(y), "f"(x));
    return r;
}

// ---------------------------------------------------------------------------
// Build B fragments: W[e,k] -> 2 RN-bf16 terms in exact mma B-fragment order.
// For (ks, t, nb, lane): e = 8*nb + lane/4, kb = 16*ks + 2*(lane%4)
//   b0 = pack(t(W[e][kb]), t(W[e][kb+1])), b1 = pack(kb+8, kb+9)
// ---------------------------------------------------------------------------
__global__ void bfrag_kernel(const float* __restrict__ W) {
    int idx = blockIdx.x * 256 + threadIdx.x;
    if (idx >= (D_DIM / 16) * 512) return;
    int l  = idx & 31;
    int nb = (idx >> 5) & 7;
    int t  = (idx >> 8) & 1;
    int ks = idx >> 9;
    int e  = 8 * nb + (l >> 2);
    int kb = 16 * ks + 2 * (l & 3);
    const float* wr = W + (size_t)e * D_DIM;
    float v0 = wr[kb], v1 = wr[kb + 1], v2 = wr[kb + 8], v3 = wr[kb + 9];
    if (t) {   // residual term: x - rn_bf16(x)
        v0 -= __bfloat162float(__float2bfloat16(v0));
        v1 -= __bfloat162float(__float2bfloat16(v1));
        v2 -= __bfloat162float(__float2bfloat16(v2));
        v3 -= __bfloat162float(__float2bfloat16(v3));
    }
    uint2 r;
    r.x = cvt_bf16x2_rn(v0, v1);
    r.y = cvt_bf16x2_rn(v2, v3);
    g_Bfrag[idx] = r;
}

// ---------------------------------------------------------------------------
// Barrier-free GEMM: 2048 independent warps; warp = 32 rows x 32 cols x K/4.
// A fragments loaded straight to registers (LDG.64), converted to 2 RN bf16
// terms in-register; B fragments via coalesced LDG.64 from g_Bfrag (L2-hot).
// 3 products (t0t0, t0t1, t1t0) per n8 block. Partials -> g_ws.
// ---------------------------------------------------------------------------
__global__ __launch_bounds__(256, 2) void gemm_kernel(const float* __restrict__ A) {
    const int wid  = threadIdx.x >> 5;
    const int lane = threadIdx.x & 31;
    const int job  = blockIdx.x * 8 + wid;   // 0..2047
    const int split = job >> 9;              // 0..3
    const int rem   = job & 511;
    const int wrow  = (rem >> 1) * 32;       // 0..8160
    const int ncb   = (rem & 1) * 4;         // n8-block base: 0 or 4
    const int r0 = lane >> 2, c0 = 2 * (lane & 3);

    // A base for this lane: row wrow+r0, col split*KSPLIT + c0
    const float* Ab = A + (size_t)(wrow + r0) * D_DIM + split * KSPLIT + c0;
    // B fragment base for this lane (uint2 units)
    const uint2* Bb = g_Bfrag + (size_t)(split * NKS) * 512 + lane;

    float acc[2][4][4];
#pragma unroll
    for (int h = 0; h < 2; h++)
#pragma unroll
        for (int nb = 0; nb < 4; nb++)
#pragma unroll
            for (int x = 0; x < 4; x++) acc[h][nb][x] = 0.0f;

    float2 ra[2][2][4];   // [buf][h][pos]  pos: {r0,c0},{r0+8,c0},{r0,c0+8},{r0+8,c0+8}
    uint2  rb[2][2][4];   // [buf][term][nb]

#define LOADT(B_, KS_) do {                                                   \
    _Pragma("unroll")                                                         \
    for (int h = 0; h < 2; h++)                                               \
        _Pragma("unroll")                                                     \
        for (int p = 0; p < 4; p++)                                           \
            ra[B_][h][p] = *(const float2*)(Ab +                              \
                (size_t)(16 * h + 8 * (p & 1)) * D_DIM + 8 * (p >> 1) +       \
                (KS_) * 16);                                                  \
    _Pragma("unroll")                                                         \
    for (int t = 0; t < 2; t++)                                               \
        _Pragma("unroll")                                                     \
        for (int nb = 0; nb < 4; nb++)                                        \
            rb[B_][t][nb] = Bb[(size_t)(KS_) * 512 + t * 256 + (ncb + nb) * 32]; \
} while (0)

#define COMPUTET(B_) do {                                                     \
    uint32_t a0[2][4], a1[2][4];                                              \
    _Pragma("unroll")                                                         \
    for (int h = 0; h < 2; h++)                                               \
        _Pragma("unroll")                                                     \
        for (int p = 0; p < 4; p++) {                                         \
            float2 v = ra[B_][h][p];                                          \
            uint32_t q = cvt_bf16x2_rn(v.x, v.y);                             \
            a0[h][p] = q;                                                     \
            float rx = v.x - __uint_as_float(q << 16);                        \
            float ry = v.y - __uint_as_float(q & 0xFFFF0000u);                \
            a1[h][p] = cvt_bf16x2_rn(rx, ry);                                 \
        }                                                                     \
    _Pragma("unroll")                                                         \
    for (int nb = 0; nb < 4; nb++)                                            \
        _Pragma("unroll")                                                     \
        for (int h = 0; h < 2; h++) {                                         \
            mma_bf16(acc[h][nb], a0[h], rb[B_][0][nb].x, rb[B_][0][nb].y);    \
            mma_bf16(acc[h][nb], a0[h], rb[B_][1][nb].x, rb[B_][1][nb].y);    \
            mma_bf16(acc[h][nb], a1[h], rb[B_][0][nb].x, rb[B_][0][nb].y);    \
        }                                                                     \
} while (0)

    LOADT(0, 0);
    for (int ks = 0; ks < NKS; ks += 2) {
        LOADT(1, ks + 1);
        COMPUTET(0);
        if (ks + 2 < NKS) LOADT(0, ks + 2);
        COMPUTET(1);
    }
#undef LOADT
#undef COMPUTET

    // store partials: C frag lane map: c0,c1 -> row r0, cols col..col+1; c2,c3 -> row r0+8
    float* wsp = g_ws + (size_t)split * (T_DIM * E_DIM) + (size_t)wrow * 64;
#pragma unroll
    for (int h = 0; h < 2; h++)
#pragma unroll
        for (int nb = 0; nb < 4; nb++) {
            const int col = (ncb + nb) * 8 + c0;
            *(float2*)(wsp + (size_t)(16 * h + r0) * 64 + col) =
                make_float2(acc[h][nb][0], acc[h][nb][1]);
            *(float2*)(wsp + (size_t)(16 * h + r0 + 8) * 64 + col) =
                make_float2(acc[h][nb][2], acc[h][nb][3]);
        }
}

// ---------------------------------------------------------------------------
// JAX threefry2x32, key=(0,42), partitionable counters; bits = o0^o1
// ---------------------------------------------------------------------------
__device__ __forceinline__ uint32_t rotl32(uint32_t x, int d) {
    return (x << d) | (x >> (32 - d));
}
__device__ __forceinline__ uint32_t threefry_bits(uint32_t j) {
    uint32_t x0 = 0u, x1 = j;
    const uint32_t k0 = 0u, k1 = 42u, k2 = 0u ^ 42u ^ 0x1BD11BDAu;
    x0 += k0; x1 += k1;
#define TF_RND(r) { x0 += x1; x1 = rotl32(x1, (r)); x1 ^= x0; }
    TF_RND(13) TF_RND(15) TF_RND(26) TF_RND(6)
    x0 += k1; x1 += k2 + 1u;
    TF_RND(17) TF_RND(29) TF_RND(16) TF_RND(24)
    x0 += k2; x1 += k0 + 2u;
    TF_RND(13) TF_RND(15) TF_RND(26) TF_RND(6)
    x0 += k0; x1 += k1 + 3u;
    TF_RND(17) TF_RND(29) TF_RND(16) TF_RND(24)
    x0 += k1; x1 += k2 + 4u;
    TF_RND(13) TF_RND(15) TF_RND(26) TF_RND(6)
    x0 += k2; x1 += k0 + 5u;
#undef TF_RND
    return x0 ^ x1;
}
__device__ __forceinline__ float bits_to_unif(uint32_t bits) {
    float f = __uint_as_float((bits >> 9) | 0x3F800000u) - 1.0f;
    const float minv = 1e-6f, maxv = 1.0f - 1e-6f;
    float v = __fadd_rn(__fmul_rn(f, maxv - minv), minv);
    return fmaxf(minv, v);
}

// ---------------------------------------------------------------------------
// Reduce splits (fixed order, deterministic) + bias -> logits; softmax +
// Gumbel top-k with exact-fp32 fallback on knife-edge rows.
// grid = 1024 CTAs x 256 threads; one warp per row.
// ---------------------------------------------------------------------------
__global__ __launch_bounds__(256) void router_kernel(
    const float* __restrict__ A,
    const float* __restrict__ Wfull,
    const float* __restrict__ bias,
    const int*  __restrict__ kptr,
    float* __restrict__ out_mask,
    float* __restrict__ out_weight,
    float* __restrict__ out_logits)
{
    __shared__ float S[8][64];
    __shared__ float vks[8][2];

    const int wid  = threadIdx.x >> 5;
    const int lane = threadIdx.x & 31;
    const int row  = blockIdx.x * 8 + wid;
    const int kk   = kptr ? *kptr : 8;
    const size_t base = (size_t)row * 64;
    const int e0 = lane, e1 = lane + 32;

    // fixed-order split reduction + bias (deterministic)
    const int TE = T_DIM * E_DIM;
    float l0 = ((g_ws[0 * TE + base + e0] + g_ws[1 * TE + base + e0]) +
                 g_ws[2 * TE + base + e0]) + g_ws[3 * TE + base + e0];
    float l1 = ((g_ws[0 * TE + base + e1] + g_ws[1 * TE + base + e1]) +
                 g_ws[2 * TE + base + e1]) + g_ws[3 * TE + base + e1];
    l0 += bias[e0];
    l1 += bias[e1];
    out_logits[base + e0] = l0;
    out_logits[base + e1] = l1;

    const uint32_t j0 = (uint32_t)(row * 64 + lane);
    const float g0 = -logf(-logf(bits_to_unif(threefry_bits(j0))));
    const float g1 = -logf(-logf(bits_to_unif(threefry_bits(j0 + 32u))));
    float sc0 = l0 + g0;
    float sc1 = l1 + g1;
    S[wid][lane]      = sc0;
    S[wid][lane + 32] = sc1;
    __syncwarp();

    // softmax weights (from mma logits; error << 1e-3 threshold)
    float m = fmaxf(l0, l1);
#pragma unroll
    for (int d2 = 16; d2 >= 1; d2 >>= 1)
        m = fmaxf(m, __shfl_xor_sync(0xFFFFFFFFu, m, d2));
    const float ex0 = expf(l0 - m);
    const float ex1 = expf(l1 - m);
    float z = ex0 + ex1;
#pragma unroll
    for (int d2 = 16; d2 >= 1; d2 >>= 1)
        z += __shfl_xor_sync(0xFFFFFFFFu, z, d2);
    const float w0 = ex0 / z;
    const float w1 = ex1 / z;

    // top-k rank count; ties -> lower index (lax.top_k stability)
    int c0 = 0, c1 = 0;
#pragma unroll 16
    for (int i = 0; i < 64; i++) {
        const float v = S[wid][i];
        c0 += (v > sc0) || (v == sc0 && i < lane);
        c1 += (v > sc1) || (v == sc1 && i < lane + 32);
    }

    // knife-edge detection: gap between rank kk-1 and rank kk
    if (c0 == kk - 1) vks[wid][0] = sc0;
    if (c1 == kk - 1) vks[wid][0] = sc1;
    if (c0 == kk)     vks[wid][1] = sc0;
    if (c1 == kk)     vks[wid][1] = sc1;
    __syncwarp();
    const bool flagged = (vks[wid][0] - vks[wid][1] < GAP_TAU);  // warp-uniform

    if (flagged) {
        // Recompute this row's logits BIT-IDENTICALLY to the verified fp32
        // kernel: sequential fma over k ascending, single accumulator, +bias.
        const float* arow = A + (size_t)row * D_DIM;
        const float* wp0  = Wfull + (size_t)e0 * D_DIM;
        const float* wp1  = Wfull + (size_t)e1 * D_DIM;
        float p0 = 0.f, p1 = 0.f;
        for (int k4 = 0; k4 < D_DIM; k4 += 4) {
            float4 av = *(const float4*)(arow + k4);
            float4 u0 = *(const float4*)(wp0 + k4);
            float4 u1 = *(const float4*)(wp1 + k4);
            p0 = fmaf(av.x, u0.x, p0); p1 = fmaf(av.x, u1.x, p1);
            p0 = fmaf(av.y, u0.y, p0); p1 = fmaf(av.y, u1.y, p1);
            p0 = fmaf(av.z, u0.z, p0); p1 = fmaf(av.z, u1.z, p1);
            p0 = fmaf(av.w, u0.w, p0); p1 = fmaf(av.w, u1.w, p1);
        }
        sc0 = (p0 + bias[e0]) + g0;
        sc1 = (p1 + bias[e1]) + g1;
        S[wid][lane]      = sc0;
        S[wid][lane + 32] = sc1;
        __syncwarp();
        c0 = 0; c1 = 0;
#pragma unroll 16
        for (int i = 0; i < 64; i++) {
            const float v = S[wid][i];
            c0 += (v > sc0) || (v == sc0 && i < lane);
            c1 += (v > sc1) || (v == sc1 && i < lane + 32);
        }
    }

    out_mask[base + e0]   = (c0 < kk) ? 1.0f : 0.0f;
    out_mask[base + e1]   = (c1 < kk) ? 1.0f : 0.0f;
    out_weight[base + e0] = w0;
    out_weight[base + e1] = w1;
}

// ---------------------------------------------------------------------------
// Output layout: tuple (mask, weight, logits) concatenated as f32.
// ---------------------------------------------------------------------------
extern "C" void kernel_launch(void* const* d_in, const int* in_sizes, int n_in,
                              void* d_out, int out_size) {
    const float* h    = (const float*)d_in[0];
    const float* W    = (const float*)d_in[1];
    const float* bias = (const float*)d_in[2];
    const int*   kptr = (n_in > 3) ? (const int*)d_in[3] : nullptr;

    float* out        = (float*)d_out;
    float* out_mask   = out;
    float* out_weight = out + (size_t)T_DIM * E_DIM;
    float* out_logits = out + 2 * (size_t)T_DIM * E_DIM;

    bfrag_kernel<<<512, 256>>>(W);
    gemm_kernel<<<256, 256>>>(h);
    router_kernel<<<T_DIM / 8, 256>>>(h, W, bias, kptr,
                                      out_mask, out_weight, out_logits);
}

// round 17
// speedup vs baseline: 1.1881x; 1.1881x over previous
#include <cuda_runtime.h>
#include <cstdint>
#include <math.h>

#define T_DIM 8192
#define D_DIM 4096
#define E_DIM 64
#define BM    64
#define KC    64
#define NT    (D_DIM / KC)      // 64 tiles

// dynamic smem layout: two buffers of (As2 32KB + Bs 16KB)
#define AS2_BYTES 32768         // 64 k x 64 rows x 8B (A duplicated f32x2)
#define BS_OFF    32768
#define BUF_BYTES 49152
#define SMEM_BYTES (2 * BUF_BYTES)   // 98304
// epilogue overlay (on buffer 0)
#define OFF_L 0
#define OFF_S 16384

// ---------------------------------------------------------------------------
// f32x2 packed helpers
// ---------------------------------------------------------------------------
__device__ __forceinline__ unsigned long long pack2(float lo, float hi) {
    unsigned long long r;
    asm("mov.b64 %0, {%1,%2};" : "=l"(r) : "f"(lo), "f"(hi));
    return r;
}
__device__ __forceinline__ float2 unpack2(unsigned long long v) {
    float2 r;
    asm("mov.b64 {%0,%1}, %2;" : "=f"(r.x), "=f"(r.y) : "l"(v));
    return r;
}
__device__ __forceinline__ void fma2(unsigned long long& d,
                                     unsigned long long a,
                                     unsigned long long b) {
    asm("fma.rn.f32x2 %0, %1, %2, %0;" : "+l"(d) : "l"(a), "l"(b));
}

// ---------------------------------------------------------------------------
// JAX threefry2x32, key=(0,42), partitionable counters; bits = o0^o1
// ---------------------------------------------------------------------------
__device__ __forceinline__ uint32_t rotl32(uint32_t x, int d) {
    return (x << d) | (x >> (32 - d));
}
__device__ __forceinline__ uint32_t threefry_bits(uint32_t j) {
    uint32_t x0 = 0u, x1 = j;
    const uint32_t k0 = 0u, k1 = 42u, k2 = 0u ^ 42u ^ 0x1BD11BDAu;
    x0 += k0; x1 += k1;
#define TF_RND(r) { x0 += x1; x1 = rotl32(x1, (r)); x1 ^= x0; }
    TF_RND(13) TF_RND(15) TF_RND(26) TF_RND(6)
    x0 += k1; x1 += k2 + 1u;
    TF_RND(17) TF_RND(29) TF_RND(16) TF_RND(24)
    x0 += k2; x1 += k0 + 2u;
    TF_RND(13) TF_RND(15) TF_RND(26) TF_RND(6)
    x0 += k0; x1 += k1 + 3u;
    TF_RND(17) TF_RND(29) TF_RND(16) TF_RND(24)
    x0 += k1; x1 += k2 + 4u;
    TF_RND(13) TF_RND(15) TF_RND(26) TF_RND(6)
    x0 += k2; x1 += k0 + 5u;
#undef TF_RND
    return x0 ^ x1;
}
__device__ __forceinline__ float bits_to_unif(uint32_t bits) {
    float f = __uint_as_float((bits >> 9) | 0x3F800000u) - 1.0f;
    const float minv = 1e-6f, maxv = 1.0f - 1e-6f;
    float v = __fadd_rn(__fmul_rn(f, maxv - minv), minv);
    return fmaxf(minv, v);
}

// ---------------------------------------------------------------------------
// Fused kernel: fp32 f32x2 GEMM (logits = h @ W^T + bias) + softmax +
// Gumbel top-k. Numerically identical to the r5-passing kernel (same
// k-ascending FFMA2 accumulation order), but with KC=64 tiles,
// double-buffered smem, and a single __syncthreads per tile.
// grid = 128 CTAs (BM=64 rows), 256 threads.
// ---------------------------------------------------------------------------
__global__ __launch_bounds__(256, 1) void router_fused_kernel(
    const float* __restrict__ A,     // h [T, D]
    const float* __restrict__ B,     // W [E=64, D]
    const float* __restrict__ bias,  // [64]
    const int*  __restrict__ kptr,
    float* __restrict__ out_mask,
    float* __restrict__ out_weight,
    float* __restrict__ out_logits)
{
    extern __shared__ __align__(1024) char sm[];

    const int tid = threadIdx.x;
    const int tx  = tid & 15;   // col group (4 cols)
    const int ty  = tid >> 4;   // row group (4 rows)
    const int bm  = blockIdx.x * 64;

    // ---- gmem load slots: 1024 float4 per tile per matrix, 4/thread ----
    const float4* Ag[4];
    const float4* Bg[4];
    int rr_[4], qq_[4];
#pragma unroll
    for (int i = 0; i < 4; i++) {
        int s = tid + i * 256;            // 0..1023
        int r = s >> 4, q = s & 15;       // row, float4-chunk in KC=64
        rr_[i] = r; qq_[i] = q;
        Ag[i] = (const float4*)(A + (size_t)(bm + r) * D_DIM) + q;
        Bg[i] = (const float4*)(B + (size_t)r * D_DIM) + q;
    }

    unsigned long long acc[4][2];
#pragma unroll
    for (int i = 0; i < 4; i++) { acc[i][0] = 0ull; acc[i][1] = 0ull; }

    // prefetch tile 0  (tile stride = KC floats = 16 float4)
    float4 ar[4], br[4];
#pragma unroll
    for (int i = 0; i < 4; i++) { ar[i] = Ag[i][0]; br[i] = Bg[i][0]; }

    for (int kt = 0; kt < NT; kt++) {
        unsigned long long* As2 =
            (unsigned long long*)(sm + (kt & 1) * BUF_BYTES);
        float* Bs = (float*)(sm + (kt & 1) * BUF_BYTES + BS_OFF);

        // ---- store prefetched tile (A duplicated f32x2; XOR swizzle) ----
#pragma unroll
        for (int i = 0; i < 4; i++) {
            const int r = rr_[i], q = qq_[i];
            const int pm = r ^ (q << 2);
            As2[(q * 4 + 0) * 64 + pm] = pack2(ar[i].x, ar[i].x);
            As2[(q * 4 + 1) * 64 + pm] = pack2(ar[i].y, ar[i].y);
            As2[(q * 4 + 2) * 64 + pm] = pack2(ar[i].z, ar[i].z);
            As2[(q * 4 + 3) * 64 + pm] = pack2(ar[i].w, ar[i].w);
            Bs[(q * 4 + 0) * 64 + pm] = br[i].x;
            Bs[(q * 4 + 1) * 64 + pm] = br[i].y;
            Bs[(q * 4 + 2) * 64 + pm] = br[i].z;
            Bs[(q * 4 + 3) * 64 + pm] = br[i].w;
        }
        __syncthreads();   // single barrier per tile

        // prefetch next tile (overlaps with compute below)
        if (kt + 1 < NT) {
            const int off = (kt + 1) * 16;   // 16 float4 per KC=64
#pragma unroll
            for (int i = 0; i < 4; i++) {
                ar[i] = Ag[i][off];
                br[i] = Bg[i][off];
            }
        }

        // ---- compute: 64 k-steps ----
#pragma unroll 32
        for (int k = 0; k < KC; k++) {
            const int sw = (k >> 2) << 2;
            const ulonglong2* ap =
                (const ulonglong2*)&As2[k * 64 + ((ty * 4) ^ sw)];
            ulonglong2 a01 = ap[0];
            ulonglong2 a23 = ap[1];
            ulonglong2 bv =
                *(const ulonglong2*)&Bs[k * 64 + ((tx * 4) ^ sw)];
            fma2(acc[0][0], a01.x, bv.x); fma2(acc[0][1], a01.x, bv.y);
            fma2(acc[1][0], a01.y, bv.x); fma2(acc[1][1], a01.y, bv.y);
            fma2(acc[2][0], a23.x, bv.x); fma2(acc[2][1], a23.x, bv.y);
            fma2(acc[3][0], a23.y, bv.x); fma2(acc[3][1], a23.y, bv.y);
        }
    }
    __syncthreads();   // last compute done before overlaying L/S on buffer 0

    // ---- epilogue: bias add, logits to gmem + smem ----
    float* L = (float*)(sm + OFF_L);
    float* S = (float*)(sm + OFF_S);
    float4 bvec = *(const float4*)(bias + tx * 4);
#pragma unroll
    for (int i = 0; i < 4; i++) {
        float2 p0 = unpack2(acc[i][0]);
        float2 p1 = unpack2(acc[i][1]);
        float4 o;
        o.x = p0.x + bvec.x;
        o.y = p0.y + bvec.y;
        o.z = p1.x + bvec.z;
        o.w = p1.y + bvec.w;
        const int rloc = ty * 4 + i;
        *(float4*)(out_logits + (size_t)(bm + rloc) * 64 + tx * 4) = o;
        *(float4*)(&L[rloc * 64 + tx * 4]) = o;
    }
    __syncthreads();

    // ---- router: softmax + Gumbel top-k, warp-per-row ----
    const int wrp = tid >> 5;          // 0..7 -> rows wrp*8 .. wrp*8+7
    const int ln  = tid & 31;          // lane: experts ln and ln+32
    const int kk  = kptr ? *kptr : 8;

    for (int rr = 0; rr < 8; rr++) {
        const int r    = wrp * 8 + rr;
        const int grow = bm + r;
        const float l0 = L[r * 64 + ln];
        const float l1 = L[r * 64 + ln + 32];

        const uint32_t j0 = (uint32_t)(grow * 64 + ln);
        const float g0 = -logf(-logf(bits_to_unif(threefry_bits(j0))));
        const float g1 = -logf(-logf(bits_to_unif(threefry_bits(j0 + 32u))));
        const float sc0 = l0 + g0;
        const float sc1 = l1 + g1;
        S[r * 64 + ln]      = sc0;
        S[r * 64 + ln + 32] = sc1;
        __syncwarp();

        // softmax: one expf per element, shfl reductions
        float m = fmaxf(l0, l1);
#pragma unroll
        for (int d = 16; d >= 1; d >>= 1)
            m = fmaxf(m, __shfl_xor_sync(0xFFFFFFFFu, m, d));
        const float e0 = expf(l0 - m);
        const float e1 = expf(l1 - m);
        float z = e0 + e1;
#pragma unroll
        for (int d = 16; d >= 1; d >>= 1)
            z += __shfl_xor_sync(0xFFFFFFFFu, z, d);
        const float w0 = e0 / z;
        const float w1 = e1 / z;

        // top-k rank count; ties -> lower index (lax.top_k stability)
        int c0 = 0, c1 = 0;
#pragma unroll 16
        for (int i = 0; i < 64; i++) {
            const float v = S[r * 64 + i];
            c0 += (v > sc0) || (v == sc0 && i < ln);
            c1 += (v > sc1) || (v == sc1 && i < ln + 32);
        }

        out_mask[j0]        = (c0 < kk) ? 1.0f : 0.0f;
        out_mask[j0 + 32u]  = (c1 < kk) ? 1.0f : 0.0f;
        out_weight[j0]       = w0;
        out_weight[j0 + 32u] = w1;
        __syncwarp();   // protect S row before next iteration reuses region
    }
}

// ---------------------------------------------------------------------------
// Output layout: tuple (mask, weight, logits) concatenated as f32.
// ---------------------------------------------------------------------------
extern "C" void kernel_launch(void* const* d_in, const int* in_sizes, int n_in,
                              void* d_out, int out_size) {
    const float* h    = (const float*)d_in[0];
    const float* W    = (const float*)d_in[1];
    const float* bias = (const float*)d_in[2];
    const int*   kptr = (n_in > 3) ? (const int*)d_in[3] : nullptr;

    float* out        = (float*)d_out;
    float* out_mask   = out;
    float* out_weight = out + (size_t)T_DIM * E_DIM;
    float* out_logits = out + 2 * (size_t)T_DIM * E_DIM;

    cudaFuncSetAttribute(router_fused_kernel,
                         cudaFuncAttributeMaxDynamicSharedMemorySize,
                         SMEM_BYTES);
    router_fused_kernel<<<T_DIM / BM, 256, SMEM_BYTES>>>(
        h, W, bias, kptr, out_mask, out_weight, out_logits);
}